// round 4
// baseline (speedup 1.0000x reference)
#include <cuda_runtime.h>

#define R    5
#define E    50000
#define NUU  20000
#define NII  20000
#define NF   4
#define DN   16
#define DR   64
#define DOUT 64

// ---------------- scratch (allocation-free: __device__ globals) ----------------
__device__ float4 g_hu[R*NUU*4];     // hu[r,n,0:16]
__device__ float4 g_hi[R*NII*4];
__device__ float  g_blend[R*E];
__device__ float  g_norm_u[NUU];
__device__ float  g_norm_i[NII];
__device__ float4 g_umsg[NUU*4];
__device__ float4 g_imsg[NII*4];

__device__ __forceinline__ float dot4(float4 a, float4 b){
    return a.x*b.x + a.y*b.y + a.z*b.z + a.w*b.w;
}

__device__ __forceinline__ void red_add_v4(float4* addr, float4 v){
    asm volatile("red.global.add.v4.f32 [%0], {%1,%2,%3,%4};"
                 :: "l"(addr), "f"(v.x), "f"(v.y), "f"(v.z), "f"(v.w)
                 : "memory");
}

// packed fp32x2 helpers (sm_103a; ptxas never auto-emits FFMA2)
__device__ __forceinline__ unsigned long long pk2(float x){
    unsigned long long r;
    asm("mov.b64 %0, {%1, %1};" : "=l"(r) : "f"(x));
    return r;
}
__device__ __forceinline__ void ffma2(unsigned long long &d,
                                      unsigned long long a, unsigned long long b){
    asm("fma.rn.f32x2 %0, %1, %2, %0;" : "+l"(d) : "l"(a), "l"(b));
}
__device__ __forceinline__ void unpk2(unsigned long long v, float &lo, float &hi){
    asm("mov.b64 {%0, %1}, %2;" : "=f"(lo), "=f"(hi) : "l"(v));
}

// ---------------- K0: zero accumulators ----------------
__global__ void __launch_bounds__(256) k_zero(){
    int i = blockIdx.x*256 + threadIdx.x;
    if (i < NUU) g_norm_u[i] = 0.f;
    if (i < NII) g_norm_i[i] = 0.f;
    float4 z = make_float4(0.f,0.f,0.f,0.f);
    if (i < NUU*4) g_umsg[i] = z;
    if (i < NII*4) g_imsg[i] = z;
}

// ---------------- K1: hu/hi = node_h[k] @ node_w^T ----------------
__global__ void __launch_bounds__(256) k_nodes(
    const float* __restrict__ user_h, const float* __restrict__ item_h,
    const float* __restrict__ w_fwd,  const float* __restrict__ w_rev,
    const int*   __restrict__ kp)
{
    __shared__ float Ws[DN*DN];
    int r = blockIdx.y, side = blockIdx.z;
    const float* W = side ? w_rev : w_fwd;
    Ws[threadIdx.x] = W[r*DN*DN + threadIdx.x];
    __syncthreads();
    int n = blockIdx.x*256 + threadIdx.x;
    if (n >= NUU) return;
    int kv = __ldg(kp);
    const float* hp = (side ? item_h : user_h) + ((size_t)(kv*R + r)*NUU + n)*DN;
    const float4* h4 = (const float4*)hp;
    float h[16];
    #pragma unroll
    for (int j=0;j<4;j++){
        float4 v = h4[j];
        h[4*j]=v.x; h[4*j+1]=v.y; h[4*j+2]=v.z; h[4*j+3]=v.w;
    }
    float4* out = (side ? g_hi : g_hu) + ((size_t)r*NUU + n)*4;
    #pragma unroll
    for (int q=0;q<4;q++){
        float acc[4];
        #pragma unroll
        for (int t=0;t<4;t++){
            int o = q*4+t;
            float a = 0.f;
            #pragma unroll
            for (int d=0; d<16; d++) a += h[d]*Ws[o*16+d];
            acc[t] = a;
        }
        out[q] = make_float4(acc[0],acc[1],acc[2],acc[3]);
    }
}

// ---------------- K2: blended weights, warp-cooperative (8 lanes / edge) ----------
__global__ void __launch_bounds__(256) k_blend(
    const float* __restrict__ user_h,    const float* __restrict__ item_h,
    const float* __restrict__ user_hsum, const float* __restrict__ item_hsum,
    const float* __restrict__ review_feat, const float* __restrict__ prototypes,
    const float* __restrict__ eta,
    const int*   __restrict__ edge_src,  const int* __restrict__ edge_dst,
    const int*   __restrict__ kp)
{
    __shared__ float4 Pr[NF*DR/4];   // 64 float4
    int r   = blockIdx.y;
    int tid = threadIdx.x;
    if (tid < NF*DR/4) Pr[tid] = ((const float4*)prototypes)[tid];
    __syncthreads();

    int g = tid >> 3;        // group (edge) within block: 0..31
    int l = tid & 7;         // lane within group
    int e = blockIdx.x*32 + g;
    bool valid = (e < E);
    int ec  = valid ? e : (E-1);      // clamp so shfl groups stay converged
    int idx = r*E + ec;
    int kv  = __ldg(kp);
    int src = __ldg(edge_src + idx);
    int dst = __ldg(edge_dst + idx);

    // ---- sim_k: cosine of user_h[k][r][src] vs item_h[k][r][dst] ----
    float uu=0.f, ii=0.f, ui=0.f;
    if (l < 4){
        float4 a = __ldg((const float4*)(user_h + ((size_t)(kv*R + r)*NUU + src)*DN) + l);
        float4 b = __ldg((const float4*)(item_h + ((size_t)(kv*R + r)*NII + dst)*DN) + l);
        uu = dot4(a,a); ii = dot4(b,b); ui = dot4(a,b);
    }
    #pragma unroll
    for (int s=1; s<8; s<<=1){
        uu += __shfl_xor_sync(0xffffffffu, uu, s, 8);
        ii += __shfl_xor_sync(0xffffffffu, ii, s, 8);
        ui += __shfl_xor_sync(0xffffffffu, ui, s, 8);
    }

    // ---- sim_all denominator: lane pair (2f,2f+1) handles factor f ----
    const float4* ru = (const float4*)(user_hsum + ((size_t)(r*NUU+src))*NF*DN);
    const float4* ci = (const float4*)(item_hsum + ((size_t)(r*NII+dst))*NF*DN);
    int off = (l>>1)*4 + (l&1)*2;
    float p = dot4(__ldg(ru+off),   __ldg(ci+off))
            + dot4(__ldg(ru+off+1), __ldg(ci+off+1));
    p += __shfl_xor_sync(0xffffffffu, p, 1, 8);     // full dot_f on both pair lanes
    float es = __expf(2.0f*p) * 0.5f;               // halve: each f counted twice
    es += __shfl_xor_sync(0xffffffffu, es, 1, 8);
    es += __shfl_xor_sync(0xffffffffu, es, 2, 8);
    es += __shfl_xor_sync(0xffffffffu, es, 4, 8);   // es = sum_f exp(sim_all_f)

    // ---- anchors: lane l covers float4s {2l, 2l+1} of each factor ----
    const float4* rf = (const float4*)(review_feat + (size_t)idx*NF*DR);
    float pa[NF];
    #pragma unroll
    for (int f=0; f<NF; f++){
        int o = f*16 + l*2;
        pa[f] = dot4(__ldg(rf+o),   Pr[o])
              + dot4(__ldg(rf+o+1), Pr[o+1]);
    }
    #pragma unroll
    for (int f=0; f<NF; f++){
        #pragma unroll
        for (int s=1; s<8; s<<=1)
            pa[f] += __shfl_xor_sync(0xffffffffu, pa[f], s, 8);
    }
    float dA = 0.f, aK = 0.f;
    #pragma unroll
    for (int f=0; f<NF; f++){
        float af = 2.0f*pa[f];
        dA += __expf(af);
        if (f == kv) aK = af;
    }

    if (l == 0 && valid){
        float den = fmaxf(sqrtf(uu),1e-12f) * fmaxf(sqrtf(ii),1e-12f);
        float sim_k = (ui/den) * 2.0f;
        float exp_sim    = __expf(sim_k)/es;
        float exp_anchor = __expf(aK)/dA;
        float et = __ldg(eta + idx);
        float gg = 1.0f/(1.0f + __expf(-et));
        float blended = gg*exp_anchor + (1.0f-gg)*exp_sim;
        g_blend[idx] = blended;
        atomicAdd(&g_norm_u[src], blended);
        atomicAdd(&g_norm_i[dst], blended);
    }
}

// ---------------- K3: w, int_dist, rfw/rfr (packed fp32x2) + message scatter ----
__global__ void __launch_bounds__(256) k_msg(
    const float* __restrict__ review_feat,
    const float* __restrict__ rw_fwd, const float* __restrict__ rw_rev,
    const int*   __restrict__ edge_src, const int* __restrict__ edge_dst,
    const int*   __restrict__ kp, float* __restrict__ out)
{
    // weights transposed to [d][o] so packed FMAs consume output pairs
    __shared__ float4 WfS4[DR*DN/4];   // 16B-aligned backing
    __shared__ float4 WrS4[DR*DN/4];
    float* WfS = (float*)WfS4;
    float* WrS = (float*)WrS4;
    int r   = blockIdx.y;
    int tid = threadIdx.x;
    for (int i = tid; i < DR*DN; i += 256){
        int d = i >> 4, o = i & 15;
        WfS[i] = rw_fwd[(size_t)r*DN*DR + o*DR + d];
        WrS[i] = rw_rev[(size_t)r*DN*DR + o*DR + d];
    }
    __syncthreads();

    int e = blockIdx.x*256 + tid;
    if (e >= E) return;
    int kv  = __ldg(kp);
    int idx = r*E + e;
    int src = __ldg(edge_src + idx);
    int dst = __ldg(edge_dst + idx);

    float b = g_blend[idx];
    float w = b * rsqrtf(g_norm_u[src]*g_norm_i[dst]);
    out[NUU*DOUT + NII*DOUT + idx] = w;   // int_dist

    // rfw/rfr: rf_k (64) x W (16x64), packed two outputs per FMA
    const float4* rfk = (const float4*)(review_feat + ((size_t)idx*NF + kv)*DR);
    unsigned long long aw[8], ar[8];
    #pragma unroll
    for (int q=0;q<8;q++){ aw[q]=0ull; ar[q]=0ull; }

    #pragma unroll 2
    for (int j=0;j<16;j++){
        float4 v = __ldg(&rfk[j]);
        #pragma unroll
        for (int c=0;c<4;c++){
            int d = 4*j + c;
            float x = (c==0)?v.x:(c==1)?v.y:(c==2)?v.z:v.w;
            unsigned long long vv = pk2(x);
            const ulonglong2* wf2 = (const ulonglong2*)(WfS + d*DN);
            const ulonglong2* wr2 = (const ulonglong2*)(WrS + d*DN);
            #pragma unroll
            for (int q=0;q<4;q++){
                ulonglong2 qf = wf2[q];
                ffma2(aw[2*q],   vv, qf.x);
                ffma2(aw[2*q+1], vv, qf.y);
                ulonglong2 qr = wr2[q];
                ffma2(ar[2*q],   vv, qr.x);
                ffma2(ar[2*q+1], vv, qr.y);
            }
        }
    }

    float accw[16], accr[16];
    #pragma unroll
    for (int q=0;q<8;q++){
        unpk2(aw[q], accw[2*q], accw[2*q+1]);
        unpk2(ar[q], accr[2*q], accr[2*q+1]);
    }

    const float4* hu = &g_hu[((size_t)r*NUU + src)*4];
    float4* im = &g_imsg[(size_t)dst*4];
    #pragma unroll
    for (int q=0;q<4;q++){
        float4 a = hu[q];
        red_add_v4(&im[q], make_float4((a.x+accw[4*q  ])*w, (a.y+accw[4*q+1])*w,
                                       (a.z+accw[4*q+2])*w, (a.w+accw[4*q+3])*w));
    }
    const float4* hi = &g_hi[((size_t)r*NII + dst)*4];
    float4* um = &g_umsg[(size_t)src*4];
    #pragma unroll
    for (int q=0;q<4;q++){
        float4 a = hi[q];
        red_add_v4(&um[q], make_float4((a.x+accr[4*q  ])*w, (a.y+accr[4*q+1])*w,
                                       (a.z+accr[4*q+2])*w, (a.w+accr[4*q+3])*w));
    }
}

// ---------------- K4: leaky_relu + FC epilogue ----------------
__global__ void __launch_bounds__(256) k_fc(
    const float* __restrict__ ufc_w, const float* __restrict__ ufc_b,
    const float* __restrict__ ifc_w, const float* __restrict__ ifc_b,
    float* __restrict__ out)
{
    int side = blockIdx.y;
    int idx  = blockIdx.x*256 + threadIdx.x;   // < NUU*DOUT
    int n = idx >> 6;
    int o = idx & 63;
    const float* W = side ? ifc_w : ufc_w;
    const float* B = side ? ifc_b : ufc_b;
    const float* msg = (const float*)(side ? g_imsg : g_umsg) + (size_t)n*DN;
    float acc = __ldg(B + o);
    #pragma unroll
    for (int j=0;j<DN;j++){
        float x = msg[j];
        x = (x > 0.f) ? x : 0.1f*x;
        acc += x * __ldg(W + o*DN + j);
    }
    out[(size_t)side*NUU*DOUT + (size_t)n*DOUT + o] = acc;
}

// ---------------- launch ----------------
extern "C" void kernel_launch(void* const* d_in, const int* in_sizes, int n_in,
                              void* d_out, int out_size)
{
    const float* user_h      = (const float*)d_in[0];
    const float* item_h      = (const float*)d_in[1];
    const float* user_hsum   = (const float*)d_in[2];
    const float* item_hsum   = (const float*)d_in[3];
    const float* review_feat = (const float*)d_in[4];
    const float* prototypes  = (const float*)d_in[5];
    const float* eta         = (const float*)d_in[6];
    const float* node_w_fwd  = (const float*)d_in[7];
    const float* review_w_fwd= (const float*)d_in[8];
    const float* node_w_rev  = (const float*)d_in[9];
    const float* review_w_rev= (const float*)d_in[10];
    const float* ufc_w       = (const float*)d_in[11];
    const float* ufc_b       = (const float*)d_in[12];
    const float* ifc_w       = (const float*)d_in[13];
    const float* ifc_b       = (const float*)d_in[14];
    const int*   edge_src    = (const int*)d_in[15];
    const int*   edge_dst    = (const int*)d_in[16];
    const int*   kp          = (const int*)d_in[17];
    float* out = (float*)d_out;

    k_zero <<<(NUU*4 + 255)/256, 256>>>();
    k_nodes<<<dim3((NUU+255)/256, R, 2), 256>>>(user_h, item_h, node_w_fwd, node_w_rev, kp);
    k_blend<<<dim3((E+31)/32, R), 256>>>(user_h, item_h, user_hsum, item_hsum,
                                         review_feat, prototypes, eta,
                                         edge_src, edge_dst, kp);
    k_msg  <<<dim3((E+255)/256, R), 256>>>(review_feat, review_w_fwd, review_w_rev,
                                           edge_src, edge_dst, kp, out);
    k_fc   <<<dim3((NUU*DOUT)/256, 2), 256>>>(ufc_w, ufc_b, ifc_w, ifc_b, out);
}

// round 6
// speedup vs baseline: 1.6171x; 1.6171x over previous
#include <cuda_runtime.h>

#define R    5
#define E    50000
#define NUU  20000
#define NII  20000
#define NF   4
#define DN   16
#define DR   64
#define DOUT 64

// ---------------- scratch (allocation-free: __device__ globals) ----------------
__device__ float4 g_hu[R*NUU*4];     // hu[r,n,0:16]
__device__ float4 g_hi[R*NII*4];
__device__ float  g_blend[R*E];
__device__ float  g_norm_u[NUU];
__device__ float  g_norm_i[NII];
__device__ float4 g_umsg[NUU*4];
__device__ float4 g_imsg[NII*4];

__device__ __forceinline__ float dot4(float4 a, float4 b){
    return a.x*b.x + a.y*b.y + a.z*b.z + a.w*b.w;
}

__device__ __forceinline__ void red_add_v4(float4* addr, float4 v){
    asm volatile("red.global.add.v4.f32 [%0], {%1,%2,%3,%4};"
                 :: "l"(addr), "f"(v.x), "f"(v.y), "f"(v.z), "f"(v.w)
                 : "memory");
}

// packed fp32x2 helpers (sm_103a; ptxas never auto-emits FFMA2)
__device__ __forceinline__ unsigned long long pk2(float x){
    unsigned long long r;
    asm("mov.b64 %0, {%1, %1};" : "=l"(r) : "f"(x));
    return r;
}
__device__ __forceinline__ void ffma2(unsigned long long &d,
                                      unsigned long long a, unsigned long long b){
    asm("fma.rn.f32x2 %0, %1, %2, %0;" : "+l"(d) : "l"(a), "l"(b));
}
__device__ __forceinline__ void unpk2(unsigned long long v, float &lo, float &hi){
    asm("mov.b64 {%0, %1}, %2;" : "=f"(lo), "=f"(hi) : "l"(v));
}

// ---------------- K0: zero accumulators ----------------
__global__ void __launch_bounds__(256) k_zero(){
    int i = blockIdx.x*256 + threadIdx.x;
    if (i < NUU) g_norm_u[i] = 0.f;
    if (i < NII) g_norm_i[i] = 0.f;
    float4 z = make_float4(0.f,0.f,0.f,0.f);
    if (i < NUU*4) g_umsg[i] = z;
    if (i < NII*4) g_imsg[i] = z;
}

// ---------------- K1: hu/hi = node_h[k] @ node_w^T ----------------
__global__ void __launch_bounds__(256) k_nodes(
    const float* __restrict__ user_h, const float* __restrict__ item_h,
    const float* __restrict__ w_fwd,  const float* __restrict__ w_rev,
    const int*   __restrict__ kp)
{
    __shared__ float Ws[DN*DN];
    int r = blockIdx.y, side = blockIdx.z;
    const float* W = side ? w_rev : w_fwd;
    Ws[threadIdx.x] = W[r*DN*DN + threadIdx.x];
    __syncthreads();
    int n = blockIdx.x*256 + threadIdx.x;
    if (n >= NUU) return;
    int kv = __ldg(kp);
    const float* hp = (side ? item_h : user_h) + ((size_t)(kv*R + r)*NUU + n)*DN;
    const float4* h4 = (const float4*)hp;
    float h[16];
    #pragma unroll
    for (int j=0;j<4;j++){
        float4 v = h4[j];
        h[4*j]=v.x; h[4*j+1]=v.y; h[4*j+2]=v.z; h[4*j+3]=v.w;
    }
    float4* out = (side ? g_hi : g_hu) + ((size_t)r*NUU + n)*4;
    #pragma unroll
    for (int q=0;q<4;q++){
        float acc[4];
        #pragma unroll
        for (int t=0;t<4;t++){
            int o = q*4+t;
            float a = 0.f;
            #pragma unroll
            for (int d=0; d<16; d++) a += h[d]*Ws[o*16+d];
            acc[t] = a;
        }
        out[q] = make_float4(acc[0],acc[1],acc[2],acc[3]);
    }
}

// ---------------- K2: blended weights, warp-cooperative (8 lanes / edge) ----------
__global__ void __launch_bounds__(256) k_blend(
    const float* __restrict__ user_h,    const float* __restrict__ item_h,
    const float* __restrict__ user_hsum, const float* __restrict__ item_hsum,
    const float* __restrict__ review_feat, const float* __restrict__ prototypes,
    const float* __restrict__ eta,
    const int*   __restrict__ edge_src,  const int* __restrict__ edge_dst,
    const int*   __restrict__ kp)
{
    __shared__ float4 Pr[NF*DR/4];   // 64 float4
    int r   = blockIdx.y;
    int tid = threadIdx.x;
    if (tid < NF*DR/4) Pr[tid] = ((const float4*)prototypes)[tid];
    __syncthreads();

    int g = tid >> 3;        // group (edge) within block: 0..31
    int l = tid & 7;         // lane within group
    int e = blockIdx.x*32 + g;
    bool valid = (e < E);
    int ec  = valid ? e : (E-1);      // clamp so shfl groups stay converged
    int idx = r*E + ec;
    int kv  = __ldg(kp);
    int src = __ldg(edge_src + idx);
    int dst = __ldg(edge_dst + idx);

    // ---- sim_k: cosine of user_h[k][r][src] vs item_h[k][r][dst] ----
    float uu=0.f, ii=0.f, ui=0.f;
    if (l < 4){
        float4 a = __ldg((const float4*)(user_h + ((size_t)(kv*R + r)*NUU + src)*DN) + l);
        float4 b = __ldg((const float4*)(item_h + ((size_t)(kv*R + r)*NII + dst)*DN) + l);
        uu = dot4(a,a); ii = dot4(b,b); ui = dot4(a,b);
    }
    #pragma unroll
    for (int s=1; s<8; s<<=1){
        uu += __shfl_xor_sync(0xffffffffu, uu, s, 8);
        ii += __shfl_xor_sync(0xffffffffu, ii, s, 8);
        ui += __shfl_xor_sync(0xffffffffu, ui, s, 8);
    }

    // ---- sim_all denominator: lane pair (2f,2f+1) handles factor f ----
    const float4* ru = (const float4*)(user_hsum + ((size_t)(r*NUU+src))*NF*DN);
    const float4* ci = (const float4*)(item_hsum + ((size_t)(r*NII+dst))*NF*DN);
    int off = (l>>1)*4 + (l&1)*2;
    float p = dot4(__ldg(ru+off),   __ldg(ci+off))
            + dot4(__ldg(ru+off+1), __ldg(ci+off+1));
    p += __shfl_xor_sync(0xffffffffu, p, 1, 8);     // full dot_f on both pair lanes
    float es = __expf(2.0f*p) * 0.5f;               // halve: each f counted twice
    es += __shfl_xor_sync(0xffffffffu, es, 1, 8);
    es += __shfl_xor_sync(0xffffffffu, es, 2, 8);
    es += __shfl_xor_sync(0xffffffffu, es, 4, 8);   // es = sum_f exp(sim_all_f)

    // ---- anchors: lane l covers float4s {2l, 2l+1} of each factor ----
    const float4* rf = (const float4*)(review_feat + (size_t)idx*NF*DR);
    float pa[NF];
    #pragma unroll
    for (int f=0; f<NF; f++){
        int o = f*16 + l*2;
        pa[f] = dot4(__ldg(rf+o),   Pr[o])
              + dot4(__ldg(rf+o+1), Pr[o+1]);
    }
    #pragma unroll
    for (int f=0; f<NF; f++){
        #pragma unroll
        for (int s=1; s<8; s<<=1)
            pa[f] += __shfl_xor_sync(0xffffffffu, pa[f], s, 8);
    }
    float dA = 0.f, aK = 0.f;
    #pragma unroll
    for (int f=0; f<NF; f++){
        float af = 2.0f*pa[f];
        dA += __expf(af);
        if (f == kv) aK = af;
    }

    if (l == 0 && valid){
        float den = fmaxf(sqrtf(uu),1e-12f) * fmaxf(sqrtf(ii),1e-12f);
        float sim_k = (ui/den) * 2.0f;
        float exp_sim    = __expf(sim_k)/es;
        float exp_anchor = __expf(aK)/dA;
        float et = __ldg(eta + idx);
        float gg = 1.0f/(1.0f + __expf(-et));
        float blended = gg*exp_anchor + (1.0f-gg)*exp_sim;
        g_blend[idx] = blended;
        atomicAdd(&g_norm_u[src], blended);
        atomicAdd(&g_norm_i[dst], blended);
    }
}

// ---------------- K3: rfw/rfr (2 edges/thread, broadcast weights) + scatter -----
__global__ void __launch_bounds__(256) k_msg(
    const float* __restrict__ review_feat,
    const float* __restrict__ rw_fwd, const float* __restrict__ rw_rev,
    const int*   __restrict__ edge_src, const int* __restrict__ edge_dst,
    const int*   __restrict__ kp, float* __restrict__ out)
{
    // weights transposed to [d][o]; rows are 64B, read as broadcast LDS.128
    __shared__ float4 WfS4[DR*DN/4];
    __shared__ float4 WrS4[DR*DN/4];
    float* WfS = (float*)WfS4;
    float* WrS = (float*)WrS4;
    int r   = blockIdx.y;
    int tid = threadIdx.x;
    for (int i = tid; i < DR*DN; i += 256){
        int d = i >> 4, o = i & 15;
        WfS[i] = rw_fwd[(size_t)r*DN*DR + o*DR + d];
        WrS[i] = rw_rev[(size_t)r*DN*DR + o*DR + d];
    }
    __syncthreads();

    int e0 = (blockIdx.x*256 + tid)*2;      // this thread: edges e0, e0+1 (E even)
    if (e0 >= E) return;
    int kv   = __ldg(kp);
    int idx0 = r*E + e0;
    int idx1 = idx0 + 1;

    const float4* rf0 = (const float4*)(review_feat + ((size_t)idx0*NF + kv)*DR);
    const float4* rf1 = rf0 + (NF*DR)/4;    // next edge is +NF*DR floats

    unsigned long long a0w[8], a0r[8], a1w[8], a1r[8];
    #pragma unroll
    for (int q=0;q<8;q++){ a0w[q]=0ull; a0r[q]=0ull; a1w[q]=0ull; a1r[q]=0ull; }

    #pragma unroll 4
    for (int jd=0; jd<16; jd++){
        float4 v0 = __ldg(rf0 + jd);
        float4 v1 = __ldg(rf1 + jd);
        float x0[4] = {v0.x, v0.y, v0.z, v0.w};
        float x1[4] = {v1.x, v1.y, v1.z, v1.w};
        #pragma unroll
        for (int c=0;c<4;c++){
            int d = 4*jd + c;
            unsigned long long p0 = pk2(x0[c]);
            unsigned long long p1 = pk2(x1[c]);
            const ulonglong2* wf2 = (const ulonglong2*)(WfS + d*DN);
            const ulonglong2* wr2 = (const ulonglong2*)(WrS + d*DN);
            #pragma unroll
            for (int q=0;q<4;q++){
                ulonglong2 f = wf2[q];              // broadcast LDS.128
                ffma2(a0w[2*q],   p0, f.x);
                ffma2(a0w[2*q+1], p0, f.y);
                ffma2(a1w[2*q],   p1, f.x);
                ffma2(a1w[2*q+1], p1, f.y);
                ulonglong2 g = wr2[q];
                ffma2(a0r[2*q],   p0, g.x);
                ffma2(a0r[2*q+1], p0, g.y);
                ffma2(a1r[2*q],   p1, g.x);
                ffma2(a1r[2*q+1], p1, g.y);
            }
        }
    }

    // ---- epilogue per edge ----
    #pragma unroll
    for (int ei=0; ei<2; ei++){
        int idx = ei ? idx1 : idx0;
        const unsigned long long* aw = ei ? a1w : a0w;
        const unsigned long long* ar = ei ? a1r : a0r;
        int src = __ldg(edge_src + idx);
        int dst = __ldg(edge_dst + idx);
        float b = g_blend[idx];
        float w = b * rsqrtf(g_norm_u[src]*g_norm_i[dst]);
        out[NUU*DOUT + NII*DOUT + idx] = w;   // int_dist

        float accw[16], accr[16];
        #pragma unroll
        for (int q=0;q<8;q++){
            unpk2(aw[q], accw[2*q], accw[2*q+1]);
            unpk2(ar[q], accr[2*q], accr[2*q+1]);
        }
        const float4* hu = &g_hu[((size_t)r*NUU + src)*4];
        float4* im = &g_imsg[(size_t)dst*4];
        #pragma unroll
        for (int q=0;q<4;q++){
            float4 a = hu[q];
            red_add_v4(&im[q], make_float4((a.x+accw[4*q  ])*w, (a.y+accw[4*q+1])*w,
                                           (a.z+accw[4*q+2])*w, (a.w+accw[4*q+3])*w));
        }
        const float4* hi = &g_hi[((size_t)r*NII + dst)*4];
        float4* um = &g_umsg[(size_t)src*4];
        #pragma unroll
        for (int q=0;q<4;q++){
            float4 a = hi[q];
            red_add_v4(&um[q], make_float4((a.x+accr[4*q  ])*w, (a.y+accr[4*q+1])*w,
                                           (a.z+accr[4*q+2])*w, (a.w+accr[4*q+3])*w));
        }
    }
}

// ---------------- K4: leaky_relu + FC epilogue ----------------
__global__ void __launch_bounds__(256) k_fc(
    const float* __restrict__ ufc_w, const float* __restrict__ ufc_b,
    const float* __restrict__ ifc_w, const float* __restrict__ ifc_b,
    float* __restrict__ out)
{
    int side = blockIdx.y;
    int idx  = blockIdx.x*256 + threadIdx.x;   // < NUU*DOUT
    int n = idx >> 6;
    int o = idx & 63;
    const float* W = side ? ifc_w : ufc_w;
    const float* B = side ? ifc_b : ufc_b;
    const float* msg = (const float*)(side ? g_imsg : g_umsg) + (size_t)n*DN;
    float acc = __ldg(B + o);
    #pragma unroll
    for (int j=0;j<DN;j++){
        float x = msg[j];
        x = (x > 0.f) ? x : 0.1f*x;
        acc += x * __ldg(W + o*DN + j);
    }
    out[(size_t)side*NUU*DOUT + (size_t)n*DOUT + o] = acc;
}

// ---------------- launch ----------------
extern "C" void kernel_launch(void* const* d_in, const int* in_sizes, int n_in,
                              void* d_out, int out_size)
{
    const float* user_h      = (const float*)d_in[0];
    const float* item_h      = (const float*)d_in[1];
    const float* user_hsum   = (const float*)d_in[2];
    const float* item_hsum   = (const float*)d_in[3];
    const float* review_feat = (const float*)d_in[4];
    const float* prototypes  = (const float*)d_in[5];
    const float* eta         = (const float*)d_in[6];
    const float* node_w_fwd  = (const float*)d_in[7];
    const float* review_w_fwd= (const float*)d_in[8];
    const float* node_w_rev  = (const float*)d_in[9];
    const float* review_w_rev= (const float*)d_in[10];
    const float* ufc_w       = (const float*)d_in[11];
    const float* ufc_b       = (const float*)d_in[12];
    const float* ifc_w       = (const float*)d_in[13];
    const float* ifc_b       = (const float*)d_in[14];
    const int*   edge_src    = (const int*)d_in[15];
    const int*   edge_dst    = (const int*)d_in[16];
    const int*   kp          = (const int*)d_in[17];
    float* out = (float*)d_out;

    k_zero <<<(NUU*4 + 255)/256, 256>>>();
    k_nodes<<<dim3((NUU+255)/256, R, 2), 256>>>(user_h, item_h, node_w_fwd, node_w_rev, kp);
    k_blend<<<dim3((E+31)/32, R), 256>>>(user_h, item_h, user_hsum, item_hsum,
                                         review_feat, prototypes, eta,
                                         edge_src, edge_dst, kp);
    k_msg  <<<dim3((E/2 + 255)/256, R), 256>>>(review_feat, review_w_fwd, review_w_rev,
                                               edge_src, edge_dst, kp, out);
    k_fc   <<<dim3((NUU*DOUT)/256, 2), 256>>>(ufc_w, ufc_b, ifc_w, ifc_b, out);
}

// round 7
// speedup vs baseline: 1.8100x; 1.1193x over previous
#include <cuda_runtime.h>

#define R    5
#define E    50000
#define NUU  20000
#define NII  20000
#define NF   4
#define DN   16
#define DR   64
#define DOUT 64

// ---------------- scratch (allocation-free: __device__ globals) ----------------
__device__ float4 g_hu[R*NUU*4];     // hu[r,n,0:16]
__device__ float4 g_hi[R*NII*4];
__device__ float  g_blend[R*E];
__device__ float  g_norm_u[NUU];
__device__ float  g_norm_i[NII];
__device__ float4 g_umsg[NUU*4];
__device__ float4 g_imsg[NII*4];

__device__ __forceinline__ float dot4(float4 a, float4 b){
    return a.x*b.x + a.y*b.y + a.z*b.z + a.w*b.w;
}

__device__ __forceinline__ void red_add_v4(float4* addr, float4 v){
    asm volatile("red.global.add.v4.f32 [%0], {%1,%2,%3,%4};"
                 :: "l"(addr), "f"(v.x), "f"(v.y), "f"(v.z), "f"(v.w)
                 : "memory");
}

// packed fp32x2 helpers (sm_103a; ptxas never auto-emits FFMA2)
__device__ __forceinline__ unsigned long long pk2(float x){
    unsigned long long r;
    asm("mov.b64 %0, {%1, %1};" : "=l"(r) : "f"(x));
    return r;
}
__device__ __forceinline__ void ffma2(unsigned long long &d,
                                      unsigned long long a, unsigned long long b){
    asm("fma.rn.f32x2 %0, %1, %2, %0;" : "+l"(d) : "l"(a), "l"(b));
}
__device__ __forceinline__ void unpk2(unsigned long long v, float &lo, float &hi){
    asm("mov.b64 {%0, %1}, %2;" : "=f"(lo), "=f"(hi) : "l"(v));
}

// ---------------- K0: zero accumulators ----------------
__global__ void __launch_bounds__(256) k_zero(){
    int i = blockIdx.x*256 + threadIdx.x;
    if (i < NUU) g_norm_u[i] = 0.f;
    if (i < NII) g_norm_i[i] = 0.f;
    float4 z = make_float4(0.f,0.f,0.f,0.f);
    if (i < NUU*4) g_umsg[i] = z;
    if (i < NII*4) g_imsg[i] = z;
}

// ---------------- K1: hu/hi = node_h[k] @ node_w^T ----------------
__global__ void __launch_bounds__(256) k_nodes(
    const float* __restrict__ user_h, const float* __restrict__ item_h,
    const float* __restrict__ w_fwd,  const float* __restrict__ w_rev,
    const int*   __restrict__ kp)
{
    __shared__ float Ws[DN*DN];
    int r = blockIdx.y, side = blockIdx.z;
    const float* W = side ? w_rev : w_fwd;
    Ws[threadIdx.x] = W[r*DN*DN + threadIdx.x];
    __syncthreads();
    int n = blockIdx.x*256 + threadIdx.x;
    if (n >= NUU) return;
    int kv = __ldg(kp);
    const float* hp = (side ? item_h : user_h) + ((size_t)(kv*R + r)*NUU + n)*DN;
    const float4* h4 = (const float4*)hp;
    float h[16];
    #pragma unroll
    for (int j=0;j<4;j++){
        float4 v = h4[j];
        h[4*j]=v.x; h[4*j+1]=v.y; h[4*j+2]=v.z; h[4*j+3]=v.w;
    }
    float4* out = (side ? g_hi : g_hu) + ((size_t)r*NUU + n)*4;
    #pragma unroll
    for (int q=0;q<4;q++){
        float acc[4];
        #pragma unroll
        for (int t=0;t<4;t++){
            int o = q*4+t;
            float a = 0.f;
            #pragma unroll
            for (int d=0; d<16; d++) a += h[d]*Ws[o*16+d];
            acc[t] = a;
        }
        out[q] = make_float4(acc[0],acc[1],acc[2],acc[3]);
    }
}

// ---------------- K2: blended weights, warp-cooperative (8 lanes / edge) ----------
__global__ void __launch_bounds__(256) k_blend(
    const float* __restrict__ user_h,    const float* __restrict__ item_h,
    const float* __restrict__ user_hsum, const float* __restrict__ item_hsum,
    const float* __restrict__ review_feat, const float* __restrict__ prototypes,
    const float* __restrict__ eta,
    const int*   __restrict__ edge_src,  const int* __restrict__ edge_dst,
    const int*   __restrict__ kp)
{
    __shared__ float4 Pr[NF*DR/4];   // 64 float4
    int r   = blockIdx.y;
    int tid = threadIdx.x;
    if (tid < NF*DR/4) Pr[tid] = ((const float4*)prototypes)[tid];
    __syncthreads();

    int g = tid >> 3;        // group (edge) within block: 0..31
    int l = tid & 7;         // lane within group
    int e = blockIdx.x*32 + g;
    bool valid = (e < E);
    int ec  = valid ? e : (E-1);      // clamp so shfl groups stay converged
    int idx = r*E + ec;
    int kv  = __ldg(kp);
    int src = __ldg(edge_src + idx);
    int dst = __ldg(edge_dst + idx);

    // ---- sim_k: cosine of user_h[k][r][src] vs item_h[k][r][dst] ----
    float uu=0.f, ii=0.f, ui=0.f;
    if (l < 4){
        float4 a = __ldg((const float4*)(user_h + ((size_t)(kv*R + r)*NUU + src)*DN) + l);
        float4 b = __ldg((const float4*)(item_h + ((size_t)(kv*R + r)*NII + dst)*DN) + l);
        uu = dot4(a,a); ii = dot4(b,b); ui = dot4(a,b);
    }
    #pragma unroll
    for (int s=1; s<8; s<<=1){
        uu += __shfl_xor_sync(0xffffffffu, uu, s, 8);
        ii += __shfl_xor_sync(0xffffffffu, ii, s, 8);
        ui += __shfl_xor_sync(0xffffffffu, ui, s, 8);
    }

    // ---- sim_all denominator: lane pair (2f,2f+1) handles factor f ----
    const float4* ru = (const float4*)(user_hsum + ((size_t)(r*NUU+src))*NF*DN);
    const float4* ci = (const float4*)(item_hsum + ((size_t)(r*NII+dst))*NF*DN);
    int off = (l>>1)*4 + (l&1)*2;
    float p = dot4(__ldg(ru+off),   __ldg(ci+off))
            + dot4(__ldg(ru+off+1), __ldg(ci+off+1));
    p += __shfl_xor_sync(0xffffffffu, p, 1, 8);     // full dot_f on both pair lanes
    float es = __expf(2.0f*p) * 0.5f;               // halve: each f counted twice
    es += __shfl_xor_sync(0xffffffffu, es, 1, 8);
    es += __shfl_xor_sync(0xffffffffu, es, 2, 8);
    es += __shfl_xor_sync(0xffffffffu, es, 4, 8);   // es = sum_f exp(sim_all_f)

    // ---- anchors: lane l covers float4s {2l, 2l+1} of each factor ----
    const float4* rf = (const float4*)(review_feat + (size_t)idx*NF*DR);
    float pa[NF];
    #pragma unroll
    for (int f=0; f<NF; f++){
        int o = f*16 + l*2;
        pa[f] = dot4(__ldg(rf+o),   Pr[o])
              + dot4(__ldg(rf+o+1), Pr[o+1]);
    }
    #pragma unroll
    for (int f=0; f<NF; f++){
        #pragma unroll
        for (int s=1; s<8; s<<=1)
            pa[f] += __shfl_xor_sync(0xffffffffu, pa[f], s, 8);
    }
    float dA = 0.f, aK = 0.f;
    #pragma unroll
    for (int f=0; f<NF; f++){
        float af = 2.0f*pa[f];
        dA += __expf(af);
        if (f == kv) aK = af;
    }

    if (l == 0 && valid){
        float den = fmaxf(sqrtf(uu),1e-12f) * fmaxf(sqrtf(ii),1e-12f);
        float sim_k = (ui/den) * 2.0f;
        float exp_sim    = __expf(sim_k)/es;
        float exp_anchor = __expf(aK)/dA;
        float et = __ldg(eta + idx);
        float gg = 1.0f/(1.0f + __expf(-et));
        float blended = gg*exp_anchor + (1.0f-gg)*exp_sim;
        g_blend[idx] = blended;
        atomicAdd(&g_norm_u[src], blended);
        atomicAdd(&g_norm_i[dst], blended);
    }
}

// ---------------- K3: rfw OR rfr (4 edges/thread, one matrix) + scatter ---------
// blockIdx.z: 0 = fwd (item messages, writes int_dist), 1 = rev (user messages)
__global__ void __launch_bounds__(256) k_msg(
    const float* __restrict__ review_feat,
    const float* __restrict__ rw_fwd, const float* __restrict__ rw_rev,
    const int*   __restrict__ edge_src, const int* __restrict__ edge_dst,
    const int*   __restrict__ kp, float* __restrict__ out)
{
    // one matrix, transposed to [d][o]; rows 64B, broadcast LDS.128
    __shared__ float4 WS4[DR*DN/4];
    float* WS = (float*)WS4;
    int r    = blockIdx.y;
    int side = blockIdx.z;              // 0=fwd, 1=rev
    int tid  = threadIdx.x;
    const float* Wsrc = side ? rw_rev : rw_fwd;
    for (int i = tid; i < DR*DN; i += 256){
        int d = i >> 4, o = i & 15;
        WS[i] = Wsrc[(size_t)r*DN*DR + o*DR + d];
    }
    __syncthreads();

    int kv = __ldg(kp);
    // 4 edges per thread, stride-256 streams within block tile of 1024 edges
    int eb = blockIdx.x*1024 + tid;
    int ev[4];  bool vd[4];
    #pragma unroll
    for (int s=0;s<4;s++){
        int e = eb + s*256;
        vd[s] = (e < E);
        ev[s] = vd[s] ? e : (E-1);
    }

    const float4* rfp[4];
    #pragma unroll
    for (int s=0;s<4;s++)
        rfp[s] = (const float4*)(review_feat + ((size_t)(r*E + ev[s])*NF + kv)*DR);

    unsigned long long acc[4][8];
    #pragma unroll
    for (int s=0;s<4;s++)
        #pragma unroll
        for (int q=0;q<8;q++) acc[s][q] = 0ull;

    #pragma unroll 4
    for (int jd=0; jd<16; jd++){
        float4 v[4];
        #pragma unroll
        for (int s=0;s<4;s++) v[s] = __ldg(rfp[s] + jd);
        #pragma unroll
        for (int c=0;c<4;c++){
            int d = 4*jd + c;
            unsigned long long p[4];
            #pragma unroll
            for (int s=0;s<4;s++){
                float x = (c==0)?v[s].x:(c==1)?v[s].y:(c==2)?v[s].z:v[s].w;
                p[s] = pk2(x);
            }
            const ulonglong2* w2 = (const ulonglong2*)(WS + d*DN);
            #pragma unroll
            for (int q=0;q<4;q++){
                ulonglong2 wq = w2[q];              // broadcast LDS.128
                #pragma unroll
                for (int s=0;s<4;s++){
                    ffma2(acc[s][2*q],   p[s], wq.x);
                    ffma2(acc[s][2*q+1], p[s], wq.y);
                }
            }
        }
    }

    // ---- epilogue per edge ----
    #pragma unroll
    for (int s=0;s<4;s++){
        if (!vd[s]) continue;
        int idx = r*E + ev[s];
        int src = __ldg(edge_src + idx);
        int dst = __ldg(edge_dst + idx);
        float b = g_blend[idx];
        float w = b * rsqrtf(g_norm_u[src]*g_norm_i[dst]);

        float a16[16];
        #pragma unroll
        for (int q=0;q<8;q++) unpk2(acc[s][q], a16[2*q], a16[2*q+1]);

        if (side == 0){
            out[NUU*DOUT + NII*DOUT + idx] = w;   // int_dist (write once)
            const float4* hu = &g_hu[((size_t)r*NUU + src)*4];
            float4* im = &g_imsg[(size_t)dst*4];
            #pragma unroll
            for (int q=0;q<4;q++){
                float4 a = hu[q];
                red_add_v4(&im[q], make_float4((a.x+a16[4*q  ])*w, (a.y+a16[4*q+1])*w,
                                               (a.z+a16[4*q+2])*w, (a.w+a16[4*q+3])*w));
            }
        } else {
            const float4* hi = &g_hi[((size_t)r*NII + dst)*4];
            float4* um = &g_umsg[(size_t)src*4];
            #pragma unroll
            for (int q=0;q<4;q++){
                float4 a = hi[q];
                red_add_v4(&um[q], make_float4((a.x+a16[4*q  ])*w, (a.y+a16[4*q+1])*w,
                                               (a.z+a16[4*q+2])*w, (a.w+a16[4*q+3])*w));
            }
        }
    }
}

// ---------------- K4: leaky_relu + FC epilogue (smem-transposed W) -------------
__global__ void __launch_bounds__(256) k_fc(
    const float* __restrict__ ufc_w, const float* __restrict__ ufc_b,
    const float* __restrict__ ifc_w, const float* __restrict__ ifc_b,
    float* __restrict__ out)
{
    __shared__ float Ws[DN*DOUT];   // transposed: Ws[j*64+o] = W[o*16+j]
    int side = blockIdx.y;
    const float* W = side ? ifc_w : ufc_w;
    const float* B = side ? ifc_b : ufc_b;
    for (int i = threadIdx.x; i < DN*DOUT; i += 256){
        int o = i >> 4, j = i & 15;         // coalesced gmem read of W
        Ws[j*DOUT + o] = W[i];
    }
    __syncthreads();

    int idx = blockIdx.x*256 + threadIdx.x;   // < NUU*DOUT
    int n = idx >> 6;
    int o = idx & 63;
    const float4* msg4 = (const float4*)((const float*)(side ? g_imsg : g_umsg) + (size_t)n*DN);
    float acc = __ldg(B + o);
    #pragma unroll
    for (int q=0;q<4;q++){
        float4 m = msg4[q];                  // warp-uniform broadcast
        float x0 = (m.x>0.f)?m.x:0.1f*m.x;
        float x1 = (m.y>0.f)?m.y:0.1f*m.y;
        float x2 = (m.z>0.f)?m.z:0.1f*m.z;
        float x3 = (m.w>0.f)?m.w:0.1f*m.w;
        acc += x0*Ws[(4*q  )*DOUT + o];
        acc += x1*Ws[(4*q+1)*DOUT + o];
        acc += x2*Ws[(4*q+2)*DOUT + o];
        acc += x3*Ws[(4*q+3)*DOUT + o];
    }
    out[(size_t)side*NUU*DOUT + (size_t)n*DOUT + o] = acc;
}

// ---------------- launch ----------------
extern "C" void kernel_launch(void* const* d_in, const int* in_sizes, int n_in,
                              void* d_out, int out_size)
{
    const float* user_h      = (const float*)d_in[0];
    const float* item_h      = (const float*)d_in[1];
    const float* user_hsum   = (const float*)d_in[2];
    const float* item_hsum   = (const float*)d_in[3];
    const float* review_feat = (const float*)d_in[4];
    const float* prototypes  = (const float*)d_in[5];
    const float* eta         = (const float*)d_in[6];
    const float* node_w_fwd  = (const float*)d_in[7];
    const float* review_w_fwd= (const float*)d_in[8];
    const float* node_w_rev  = (const float*)d_in[9];
    const float* review_w_rev= (const float*)d_in[10];
    const float* ufc_w       = (const float*)d_in[11];
    const float* ufc_b       = (const float*)d_in[12];
    const float* ifc_w       = (const float*)d_in[13];
    const float* ifc_b       = (const float*)d_in[14];
    const int*   edge_src    = (const int*)d_in[15];
    const int*   edge_dst    = (const int*)d_in[16];
    const int*   kp          = (const int*)d_in[17];
    float* out = (float*)d_out;

    k_zero <<<(NUU*4 + 255)/256, 256>>>();
    k_nodes<<<dim3((NUU+255)/256, R, 2), 256>>>(user_h, item_h, node_w_fwd, node_w_rev, kp);
    k_blend<<<dim3((E+31)/32, R), 256>>>(user_h, item_h, user_hsum, item_hsum,
                                         review_feat, prototypes, eta,
                                         edge_src, edge_dst, kp);
    k_msg  <<<dim3((E+1023)/1024, R, 2), 256>>>(review_feat, review_w_fwd, review_w_rev,
                                                edge_src, edge_dst, kp, out);
    k_fc   <<<dim3((NUU*DOUT)/256, 2), 256>>>(ufc_w, ufc_b, ifc_w, ifc_b, out);
}